// round 5
// baseline (speedup 1.0000x reference)
#include <cuda_runtime.h>

#define DD 96
#define HH 192
#define WW 192
#define W4N (WW/4)                // 48
#define NFULL (DD*HH*WW)          // 3538944
#define NQ    (NFULL/4)
#define NL1 (48*96*96)            // 442368
#define NL2 (24*48*48)            // 55296
#define NL3 (12*24*24)            // 6912

#define DT   0.01f
#define RE   0.001f
#define INVD (-1.0f/6.0f)         // 1/diag, diag = -6

// ---------------- scratch (device globals, float4-aligned) ----------------
__device__ float4 g_U4[NQ], g_V4[NQ], g_W4[NQ], g_INV4[NQ];
__device__ float4 g_BU4[NQ], g_BV4[NQ], g_BW4[NQ];
__device__ float4 g_B4[NQ], g_R04[NQ], g_R0b4[NQ], g_P4[NQ];
__device__ float g_R1[NL1], g_R2[NL2], g_R3[NL3];
__device__ float g_W2[NL2], g_W1[NL1];

// ---------------- helpers ----------------
__device__ __forceinline__ float g(const float4 v, int k) {
    switch (k) { case 0: return v.x; case 1: return v.y; case 2: return v.z; default: return v.w; }
}
__device__ __forceinline__ void setk(float4& v, int k, float val) {
    switch (k) { case 0: v.x = val; break; case 1: v.y = val; break;
                 case 2: v.z = val; break; default: v.w = val; }
}

struct St { float4 c, ym, yp, zm, zp; float xm, xp; };
struct PRow { float4 c, ym, yp; float xm, xp; };

__device__ __forceinline__ float4 loadC(const float* __restrict__ f, int z, int y, int x4) {
    if ((unsigned)z >= (unsigned)DD) return make_float4(0,0,0,0);
    return ((const float4*)f)[(z*HH + y)*W4N + x4];
}

__device__ __forceinline__ PRow loadPRowC(const float* __restrict__ f, int z, int y, int x4,
                                          float4 c_known) {
    PRow r;
    r.c = c_known;
    const float4* f4 = (const float4*)f;
    r.ym = (y > 0)    ? f4[(z*HH + y-1)*W4N + x4] : make_float4(0,0,0,0);
    r.yp = (y < HH-1) ? f4[(z*HH + y+1)*W4N + x4] : make_float4(0,0,0,0);
    int base = (z*HH + y)*WW + 4*x4;
    r.xm = (x4 > 0)     ? f[base - 1] : 0.0f;
    r.xp = (x4 < W4N-1) ? f[base + 4] : 0.0f;
    return r;
}
__device__ __forceinline__ PRow loadPRow(const float* __restrict__ f, int z, int y, int x4) {
    return loadPRowC(f, z, y, x4, loadC(f, z, y, x4));
}

__device__ __forceinline__ St gather(const float* __restrict__ f, int z, int y, int x4) {
    St s;
    const float4* f4 = (const float4*)f;
    s.c  = f4[(z*HH + y)*W4N + x4];
    s.ym = (y > 0)    ? f4[(z*HH + y-1)*W4N + x4]   : make_float4(0,0,0,0);
    s.yp = (y < HH-1) ? f4[(z*HH + y+1)*W4N + x4]   : make_float4(0,0,0,0);
    s.zm = (z > 0)    ? f4[((z-1)*HH + y)*W4N + x4] : make_float4(0,0,0,0);
    s.zp = (z < DD-1) ? f4[((z+1)*HH + y)*W4N + x4] : make_float4(0,0,0,0);
    int base = (z*HH + y)*WW + 4*x4;
    s.xm = (x4 > 0)     ? f[base - 1] : 0.0f;
    s.xp = (x4 < W4N-1) ? f[base + 4] : 0.0f;
    return s;
}

__device__ __forceinline__ void damp(St& a, const St& s) {
    a.c.x*=s.c.x;   a.c.y*=s.c.y;   a.c.z*=s.c.z;   a.c.w*=s.c.w;
    a.ym.x*=s.ym.x; a.ym.y*=s.ym.y; a.ym.z*=s.ym.z; a.ym.w*=s.ym.w;
    a.yp.x*=s.yp.x; a.yp.y*=s.yp.y; a.yp.z*=s.yp.z; a.yp.w*=s.yp.w;
    a.zm.x*=s.zm.x; a.zm.y*=s.zm.y; a.zm.z*=s.zm.z; a.zm.w*=s.zm.w;
    a.zp.x*=s.zp.x; a.zp.y*=s.zp.y; a.zp.z*=s.zp.z; a.zp.w*=s.zp.w;
    a.xm*=s.xm;     a.xp*=s.xp;
}

// neighbors of component k within a gathered stencil (St)
#define NBRS(sf, k, fc, fxm, fxp, fym, fyp, fzm, fzp)                       \
    float fc  = g((sf).c, k);                                               \
    float fxm = (k)     ? g((sf).c, (k)-1) : (sf).xm;                       \
    float fxp = ((k)<3) ? g((sf).c, (k)+1) : (sf).xp;                       \
    float fym = g((sf).ym, k), fyp = g((sf).yp, k);                         \
    float fzm = g((sf).zm, k), fzp = g((sf).zp, k);

// neighbors of component k from a PRow + separate z-planes
#define NBRSR(row, zmv, zpv, k, fc, fxm, fxp, fym, fyp, fzm, fzp)           \
    float fc  = g((row).c, k);                                              \
    float fxm = (k)     ? g((row).c, (k)-1) : (row).xm;                     \
    float fxp = ((k)<3) ? g((row).c, (k)+1) : (row).xp;                     \
    float fym = g((row).ym, k), fyp = g((row).yp, k);                       \
    float fzm = g((zmv), k),    fzp = g((zpv), k);

// W1 prolongation fetch (zero outside domain)
__device__ __forceinline__ float wmat(const float* __restrict__ w1, int z, int y, int x) {
    if ((unsigned)z >= (unsigned)DD || (unsigned)y >= (unsigned)HH || (unsigned)x >= (unsigned)WW)
        return 0.0f;
    return w1[((z>>1)*(HH/2) + (y>>1))*(WW/2) + (x>>1)];
}

// ---------------- stage 0: INV = 1/(1+dt*sigma) ----------------
__global__ __launch_bounds__(256) void k_inv(const float4* __restrict__ sg) {
    int i = blockIdx.x*blockDim.x + threadIdx.x;
    if (i >= NQ) return;
    float4 s = sg[i];
    float4 inv;
    inv.x = 1.0f/(1.0f + DT*s.x);
    inv.y = 1.0f/(1.0f + DT*s.y);
    inv.z = 1.0f/(1.0f + DT*s.z);
    inv.w = 1.0f/(1.0f + DT*s.w);
    g_INV4[i] = inv;
}

// ---------------- predictor: BU/BV/BW ----------------
__global__ __launch_bounds__(192) void k_pred(const float* __restrict__ vu,
                                              const float* __restrict__ vv,
                                              const float* __restrict__ vw,
                                              const float* __restrict__ vp) {
    const float* INV = (const float*)g_INV4;
    int x4 = threadIdx.x, y = blockIdx.x*4 + threadIdx.y, z = blockIdx.y;

    St si = gather(INV, z, y, x4);
    St su = gather(vu, z, y, x4); damp(su, si);
    St sv = gather(vv, z, y, x4); damp(sv, si);
    St sw = gather(vw, z, y, x4); damp(sw, si);
    St sp = gather(vp, z, y, x4);

    float4 bu4, bv4, bw4;
#pragma unroll
    for (int k = 0; k < 4; k++) {
        int x = 4*x4 + k;
        int nout = (x==0)+(x==WW-1)+(y==0)+(y==HH-1)+(z==0)+(z==DD-1);
        float hn = 0.5f * (float)nout;
        float invc = g(si.c, k);

        NBRS(su, k, uc, uxm, uxp, uym, uyp, uzm, uzp);
        NBRS(sv, k, vc, vxm, vxp, vym, vyp, vzm, vzp);
        NBRS(sw, k, wc, wxm, wxp, wym, wyp, wzm, wzp);
        NBRS(sp, k, pc, pxm, pxp, pym, pyp, pzm, pzp);
        (void)pc;

        float dxp = 0.5f*(pxp-pxm), dyp = 0.5f*(pyp-pym), dzp = 0.5f*(pzp-pzm);

        float ku = (uxm+uxp+uym+uyp+uzm+uzp - 6.0f*uc) + hn*uc;
        float kv = (vxm+vxp+vym+vyp+vzm+vzp - 6.0f*vc) + hn*vc;
        float kw = (wxm+wxp+wym+wyp+wzm+wzp - 6.0f*wc) + hn*wc;

        float dxu = 0.5f*(uxp-uxm), dyu = 0.5f*(uyp-uym), dzu = 0.5f*(uzp-uzm);
        float dxv = 0.5f*(vxp-vxm), dyv = 0.5f*(vyp-vym), dzv = 0.5f*(vzp-vzm);
        float dxw = 0.5f*(wxp-wxm), dyw = 0.5f*(wyp-wym), dzw = 0.5f*(wzp-wzm);

        setk(bu4, k, (uc + 0.5f*(RE*ku*DT - uc*dxu*DT - vc*dyu*DT - wc*dzu*DT) - dxp*DT) * invc);
        setk(bv4, k, (vc + 0.5f*(RE*kv*DT - uc*dxv*DT - vc*dyv*DT - wc*dzv*DT) - dyp*DT) * invc);
        setk(bw4, k, (wc + 0.5f*(RE*kw*DT - uc*dxw*DT - vc*dyw*DT - wc*dzw*DT) - dzp*DT) * invc);
    }
    int i4 = (z*HH + y)*W4N + x4;
    g_BU4[i4] = bu4; g_BV4[i4] = bv4; g_BW4[i4] = bw4;
}

// ---------------- corrector: write U,V,W ----------------
__global__ __launch_bounds__(192) void k_stage3(const float* __restrict__ vu,
                                                const float* __restrict__ vv,
                                                const float* __restrict__ vw,
                                                const float* __restrict__ vp) {
    const float* BU = (const float*)g_BU4;
    const float* BV = (const float*)g_BV4;
    const float* BW = (const float*)g_BW4;
    int x4 = threadIdx.x, y = blockIdx.x*4 + threadIdx.y, z = blockIdx.y;
    int i4 = (z*HH + y)*W4N + x4;

    St sbu = gather(BU, z, y, x4);
    St sbv = gather(BV, z, y, x4);
    St sbw = gather(BW, z, y, x4);
    St sp  = gather(vp, z, y, x4);

    float4 inv4 = g_INV4[i4];
    float4 u0 = ((const float4*)vu)[i4];
    float4 v0 = ((const float4*)vv)[i4];
    float4 w0 = ((const float4*)vw)[i4];

    float4 un4, vn4, wn4;
#pragma unroll
    for (int k = 0; k < 4; k++) {
        int x = 4*x4 + k;
        int nout = (x==0)+(x==WW-1)+(y==0)+(y==HH-1)+(z==0)+(z==DD-1);
        float hn = 0.5f * (float)nout;
        float invc = g(inv4, k);
        float uc = g(u0,k)*invc, vc = g(v0,k)*invc, wc = g(w0,k)*invc;

        NBRS(sbu, k, buc, buxm, buxp, buym, buyp, buzm, buzp);
        NBRS(sbv, k, bvc, bvxm, bvxp, bvym, bvyp, bvzm, bvzp);
        NBRS(sbw, k, bwc, bwxm, bwxp, bwym, bwyp, bwzm, bwzp);
        NBRS(sp,  k, pc,  pxm,  pxp,  pym,  pyp,  pzm,  pzp);
        (void)pc;

        float dxp = 0.5f*(pxp-pxm), dyp = 0.5f*(pyp-pym), dzp = 0.5f*(pzp-pzm);

        float kub = (buxm+buxp+buym+buyp+buzm+buzp - 6.0f*buc) + hn*buc;
        float kvb = (bvxm+bvxp+bvym+bvyp+bvzm+bvzp - 6.0f*bvc) + hn*bvc;
        float kwb = (bwxm+bwxp+bwym+bwyp+bwzm+bwzp - 6.0f*bwc) + hn*bwc;

        float dx_bu=0.5f*(buxp-buxm), dy_bu=0.5f*(buyp-buym), dz_bu=0.5f*(buzp-buzm);
        float dx_bv=0.5f*(bvxp-bvxm), dy_bv=0.5f*(bvyp-bvym), dz_bv=0.5f*(bvzp-bvzm);
        float dx_bw=0.5f*(bwxp-bwxm), dy_bw=0.5f*(bwyp-bwym), dz_bw=0.5f*(bwzp-bwzm);

        setk(un4, k, (uc + RE*kub*DT - buc*dx_bu*DT - bvc*dy_bu*DT - bwc*dz_bu*DT - dxp*DT) * invc);
        setk(vn4, k, (vc + RE*kvb*DT - buc*dx_bv*DT - bvc*dy_bv*DT - bwc*dz_bv*DT - dyp*DT) * invc);
        setk(wn4, k, (wc + RE*kwb*DT - buc*dx_bw*DT - bvc*dy_bw*DT - bwc*dz_bw*DT - dzp*DT) * invc);
    }
    g_U4[i4] = un4; g_V4[i4] = vn4; g_W4[i4] = wn4;
}

// ---------------- fused rhs + fine residual (iter 1), z-march ZRB ----------------
#define ZRB 8
__global__ __launch_bounds__(192) void k_residb(const float* __restrict__ vp) {
    const float* U = (const float*)g_U4;
    const float* V = (const float*)g_V4;
    const float* W = (const float*)g_W4;
    int x4 = threadIdx.x, y = blockIdx.x*4 + threadIdx.y, z0 = blockIdx.y*ZRB;

    float4 p_zm = loadC(vp, z0-1, y, x4);
    PRow  prow  = loadPRow(vp, z0, y, x4);
    float4 w_zm = loadC(W, z0-1, y, x4);
    float4 w_c  = loadC(W, z0,   y, x4);

#pragma unroll
    for (int zi = 0; zi < ZRB; zi++) {
        int z = z0 + zi;
        int i4 = (z*HH + y)*W4N + x4;

        float4 p_zp = loadC(vp, z+1, y, x4);
        float4 w_zp = loadC(W,  z+1, y, x4);

        float4 ucv = ((const float4*)U)[i4];
        int base = (z*HH + y)*WW + 4*x4;
        float uxm_s = (x4 > 0)     ? U[base - 1] : 0.0f;
        float uxp_s = (x4 < W4N-1) ? U[base + 4] : 0.0f;

        const float4* V4 = (const float4*)V;
        float4 vym = (y > 0)    ? V4[(z*HH + y-1)*W4N + x4] : make_float4(0,0,0,0);
        float4 vyp = (y < HH-1) ? V4[(z*HH + y+1)*W4N + x4] : make_float4(0,0,0,0);

        float4 b4, r4;
#pragma unroll
        for (int k = 0; k < 4; k++) {
            float uxm = k ? g(ucv,k-1) : uxm_s;
            float uxp = (k<3) ? g(ucv,k+1) : uxp_s;
            float dxu = 0.5f*(uxp - uxm);
            float dyv = 0.5f*(g(vyp,k) - g(vym,k));
            float dzw = 0.5f*(g(w_zp,k) - g(w_zm,k));
            float b = -(dxu + dyv + dzw) * (1.0f/DT);

            NBRSR(prow, p_zm, p_zp, k, pc, pxm, pxp, pym, pyp, pzm, pzp);
            float lap = pxm+pxp+pym+pyp+pzm+pzp - 6.0f*pc;
            setk(b4, k, b);
            setk(r4, k, lap - b);
        }
        g_B4[i4] = b4;
        g_R04[i4] = r4;

        // rotate
        p_zm = prow.c;
        if (zi < ZRB-1) prow = loadPRowC(vp, z+1, y, x4, p_zp);
        w_zm = w_c; w_c = w_zp;
    }
}

// ---------------- fused 3-level restriction: R0->R1,R2,R3 in one pass ----------------
__global__ __launch_bounds__(64) void k_restrict3(const float* __restrict__ src) {
    // block = one R3 cell = 8x8x8 fine region; R3 dims 12x24x24
    int cell = blockIdx.x;
    int x3 = cell % 24, t = cell / 24, y3 = t % 24, z3 = t / 24;
    int tid = threadIdx.x;                 // 0..63 -> one R1 cell (2x2x2 fine)
    int x1 = tid & 3, y1 = (tid >> 2) & 3, z1 = tid >> 4;

    int fz = z3*8 + z1*2, fy = y3*8 + y1*2, fx = x3*8 + x1*2;
    const float* s = src + ((size_t)fz*HH + fy)*WW + fx;
    float2 a0 = *(const float2*)(s);
    float2 a1 = *(const float2*)(s + WW);
    float2 a2 = *(const float2*)(s + HH*WW);
    float2 a3 = *(const float2*)(s + HH*WW + WW);
    float r1 = 0.125f*(a0.x+a0.y+a1.x+a1.y+a2.x+a2.y+a3.x+a3.y);
    g_R1[((z3*4+z1)*96 + (y3*4+y1))*96 + (x3*4+x1)] = r1;

    __shared__ float sm1[64];
    __shared__ float sm2[8];
    sm1[tid] = r1;
    __syncthreads();
    if (tid < 8) {
        int x2 = tid & 1, y2 = (tid >> 1) & 1, z2 = tid >> 2;
        float r2 = 0.0f;
#pragma unroll
        for (int dz = 0; dz < 2; dz++)
#pragma unroll
            for (int dy = 0; dy < 2; dy++)
#pragma unroll
                for (int dx = 0; dx < 2; dx++)
                    r2 += sm1[((2*z2+dz)<<4) | ((2*y2+dy)<<2) | (2*x2+dx)];
        r2 *= 0.125f;
        g_R2[((z3*2+z2)*48 + (y3*2+y2))*48 + (x3*2+x2)] = r2;
        sm2[tid] = r2;
    }
    __syncthreads();
    if (tid == 0) {
        float r3 = 0.0f;
#pragma unroll
        for (int j = 0; j < 8; j++) r3 += sm2[j];
        g_R3[(z3*24 + y3)*24 + x3] = 0.125f * r3;
    }
}

// ---- prolong(coarse)*cscale then Jacobi smooth: out = w - A0(w)/diag + r/diag ----
__global__ void k_smooth(const float* __restrict__ coarse, const float* __restrict__ r,
                         float* __restrict__ out, int dz, int dy, int dx, float cscale) {
    int i = blockIdx.x*blockDim.x + threadIdx.x;
    int n = dz*dy*dx;
    if (i >= n) return;
    int x = i % dx, t = i / dx, y = t % dy, z = t / dy;
    int cy = dy >> 1, cx = dx >> 1;
    auto wp = [&](int zz, int yy, int xx) -> float {
        if ((unsigned)zz >= (unsigned)dz || (unsigned)yy >= (unsigned)dy || (unsigned)xx >= (unsigned)dx)
            return 0.0f;
        return cscale * coarse[((zz>>1)*cy + (yy>>1))*cx + (xx>>1)];
    };
    float c = wp(z,y,x);
    float a = wp(z,y,x-1)+wp(z,y,x+1)+wp(z,y-1,x)+wp(z,y+1,x)+wp(z-1,y,x)+wp(z+1,y,x) - 6.0f*c;
    out[i] = c - a*INVD + r[i]*INVD;
}

// -------- fused iter-1 p-update + iter-2 residual, z-march ZP ----------------
#define ZP 4
__global__ __launch_bounds__(192) void k_pup_resid(const float* __restrict__ vp) {
    const float* R0 = (const float*)g_R04;
    int x4 = threadIdx.x, y = blockIdx.x*4 + threadIdx.y, z0 = blockIdx.y*ZP;

    float4 p_zm = loadC(vp, z0-1, y, x4);
    PRow  prow  = loadPRow(vp, z0, y, x4);
    float4 r_zm = loadC(R0, z0-1, y, x4);
    PRow  rrow  = loadPRow(R0, z0, y, x4);

#pragma unroll
    for (int zi = 0; zi < ZP; zi++) {
        int z = z0 + zi;
        int i4 = (z*HH + y)*W4N + x4;

        float4 p_zp = loadC(vp, z+1, y, x4);
        float4 r_zp = loadC(R0, z+1, y, x4);
        float4 b4 = g_B4[i4];

        float4 p4, rr4;
#pragma unroll
        for (int k = 0; k < 4; k++) {
            int x = 4*x4 + k;
            NBRSR(prow, p_zm, p_zp, k, pc, pxm, pxp, pym, pyp, pzm, pzp);
            NBRSR(rrow, r_zm, r_zp, k, rc, rxm, rxp, rym, ryp, rzm, rzp);

            float p1c  = pc  - wmat(g_W1, z, y, x)   - rc  * INVD;
            float p1xm = pxm - wmat(g_W1, z, y, x-1) - rxm * INVD;
            float p1xp = pxp - wmat(g_W1, z, y, x+1) - rxp * INVD;
            float p1ym = pym - wmat(g_W1, z, y-1, x) - rym * INVD;
            float p1yp = pyp - wmat(g_W1, z, y+1, x) - ryp * INVD;
            float p1zm = pzm - wmat(g_W1, z-1, y, x) - rzm * INVD;
            float p1zp = pzp - wmat(g_W1, z+1, y, x) - rzp * INVD;

            float lap = p1xm+p1xp+p1ym+p1yp+p1zm+p1zp - 6.0f*p1c;
            setk(p4, k, p1c);
            setk(rr4, k, lap - g(b4, k));
        }
        g_P4[i4] = p4;
        g_R0b4[i4] = rr4;

        p_zm = prow.c;
        r_zm = rrow.c;
        if (zi < ZP-1) {
            prow = loadPRowC(vp, z+1, y, x4, p_zp);
            rrow = loadPRowC(R0, z+1, y, x4, r_zp);
        }
    }
}

// -------- fused iter-2 p-update + final projection + sb, z-march ZP --------
__global__ __launch_bounds__(192) void k_pfinal(float* __restrict__ out_p, float* __restrict__ out_wmg,
                                                float* __restrict__ ou, float* __restrict__ ov,
                                                float* __restrict__ ow) {
    const float* P  = (const float*)g_P4;
    const float* R0 = (const float*)g_R0b4;
    int x4 = threadIdx.x, y = blockIdx.x*4 + threadIdx.y, z0 = blockIdx.y*ZP;

    float4 p_zm = loadC(P, z0-1, y, x4);
    PRow  prow  = loadPRow(P, z0, y, x4);
    float4 r_zm = loadC(R0, z0-1, y, x4);
    PRow  rrow  = loadPRow(R0, z0, y, x4);

#pragma unroll
    for (int zi = 0; zi < ZP; zi++) {
        int z = z0 + zi;
        int i4 = (z*HH + y)*W4N + x4;

        float4 p_zp = loadC(P, z+1, y, x4);
        float4 r_zp = loadC(R0, z+1, y, x4);

        float4 u4 = g_U4[i4], v4 = g_V4[i4], w4 = g_W4[i4], inv4 = g_INV4[i4];

        float4 op4, owm4, ou4, ov4, ow4;
#pragma unroll
        for (int k = 0; k < 4; k++) {
            int x = 4*x4 + k;
            NBRSR(prow, p_zm, p_zp, k, pc, pxm, pxp, pym, pyp, pzm, pzp);
            NBRSR(rrow, r_zm, r_zp, k, rc, rxm, rxp, rym, ryp, rzm, rzp);

            float wm   = wmat(g_W1, z, y, x);
            float p2c  = pc  - wm                    - rc  * INVD;
            float p2xm = pxm - wmat(g_W1, z, y, x-1) - rxm * INVD;
            float p2xp = pxp - wmat(g_W1, z, y, x+1) - rxp * INVD;
            float p2ym = pym - wmat(g_W1, z, y-1, x) - rym * INVD;
            float p2yp = pyp - wmat(g_W1, z, y+1, x) - ryp * INVD;
            float p2zm = pzm - wmat(g_W1, z-1, y, x) - rzm * INVD;
            float p2zp = pzp - wmat(g_W1, z+1, y, x) - rzp * INVD;

            float dxp = 0.5f*(p2xp - p2xm);
            float dyp = 0.5f*(p2yp - p2ym);
            float dzp = 0.5f*(p2zp - p2zm);

            float invc = g(inv4, k);
            setk(op4, k, p2c);
            setk(owm4, k, wm);
            setk(ou4, k, (g(u4,k) - dxp*DT) * invc);
            setk(ov4, k, (g(v4,k) - dyp*DT) * invc);
            setk(ow4, k, (g(w4,k) - dzp*DT) * invc);
        }
        ((float4*)out_p)[i4]   = op4;
        ((float4*)out_wmg)[i4] = owm4;
        ((float4*)ou)[i4] = ou4;
        ((float4*)ov)[i4] = ov4;
        ((float4*)ow)[i4] = ow4;

        p_zm = prow.c;
        r_zm = rrow.c;
        if (zi < ZP-1) {
            prow = loadPRowC(P, z+1, y, x4, p_zp);
            rrow = loadPRowC(R0, z+1, y, x4, r_zp);
        }
    }
}

// ---------------- launch ----------------
extern "C" void kernel_launch(void* const* d_in, const int* in_sizes, int n_in,
                              void* d_out, int out_size) {
    const float* vu = (const float*)d_in[0];
    const float* vv = (const float*)d_in[1];
    const float* vw = (const float*)d_in[2];
    const float* vp = (const float*)d_in[3];
    const float* sg = (const float*)d_in[4];

    float* out     = (float*)d_out;
    float* out_u   = out;
    float* out_v   = out + (size_t)NFULL;
    float* out_w   = out + (size_t)2*NFULL;
    float* out_p   = out + (size_t)3*NFULL;
    float* out_wmg = out + (size_t)4*NFULL;
    float* out_r   = out + (size_t)5*NFULL;

    void *pR0, *pR0b, *pR1, *pR2, *pR3, *pW2, *pW1;
    cudaGetSymbolAddress(&pR0,  g_R04);
    cudaGetSymbolAddress(&pR0b, g_R0b4);
    cudaGetSymbolAddress(&pR1,  g_R1);
    cudaGetSymbolAddress(&pR2,  g_R2);
    cudaGetSymbolAddress(&pR3,  g_R3);
    cudaGetSymbolAddress(&pW2,  g_W2);
    cudaGetSymbolAddress(&pW1,  g_W1);

    dim3 blk(W4N, 4, 1);          // 192 threads
    dim3 grd(HH/4, DD);
    dim3 grdR(HH/4, DD/ZRB);
    dim3 grdP(HH/4, DD/ZP);

    k_inv   <<<(NQ+255)/256, 256>>>((const float4*)sg);
    k_pred  <<<grd, blk>>>(vu, vv, vw, vp);
    k_stage3<<<grd, blk>>>(vu, vv, vw, vp);

    // ---- MG iteration 1 (p = vp) ----
    k_residb<<<grdR, blk>>>(vp);
    k_restrict3<<<NL3, 64>>>((const float*)pR0);
    k_smooth<<<(NL2+255)/256, 256>>>((const float*)pR3, (const float*)pR2, (float*)pW2,
                                     24, 48, 48, INVD);
    k_smooth<<<(NL1+255)/256, 256>>>((const float*)pW2, (const float*)pR1, (float*)pW1,
                                     48, 96, 96, 1.0f);

    // ---- fused: P = p1; R0b = A(p1) - b ----
    k_pup_resid<<<grdP, blk>>>(vp);

    // ---- MG iteration 2 coarse solve ----
    k_restrict3<<<NL3, 64>>>((const float*)pR0b);
    k_smooth<<<(NL2+255)/256, 256>>>((const float*)pR3, (const float*)pR2, (float*)pW2,
                                     24, 48, 48, INVD);
    k_smooth<<<(NL1+255)/256, 256>>>((const float*)pW2, (const float*)pR1, (float*)pW1,
                                     48, 96, 96, 1.0f);

    k_pfinal<<<grdP, blk>>>(out_p, out_wmg, out_u, out_v, out_w);
    cudaMemcpyAsync(out_r, pR3, NL3*sizeof(float), cudaMemcpyDeviceToDevice);
}

// round 6
// speedup vs baseline: 1.0212x; 1.0212x over previous
#include <cuda_runtime.h>

#define DD 96
#define HH 192
#define WW 192
#define W4N (WW/4)                // 48
#define NFULL (DD*HH*WW)          // 3538944
#define NQ    (NFULL/4)
#define NL1 (48*96*96)            // 442368
#define NL2 (24*48*48)            // 55296
#define NL3 (12*24*24)            // 6912

#define DT   0.01f
#define RE   0.001f
#define INVD (-1.0f/6.0f)         // 1/diag, diag = -6

// ---------------- scratch (device globals, float4-aligned) ----------------
__device__ float4 g_U4[NQ], g_V4[NQ], g_W4[NQ], g_INV4[NQ];
__device__ float4 g_B4[NQ], g_R04[NQ], g_R0b4[NQ], g_P4[NQ];
__device__ float g_R1[NL1], g_R2[NL2], g_R3[NL3];
__device__ float g_W2[NL2], g_W1[NL1];

// ---------------- helpers ----------------
__device__ __forceinline__ float g(const float4 v, int k) {
    switch (k) { case 0: return v.x; case 1: return v.y; case 2: return v.z; default: return v.w; }
}
__device__ __forceinline__ void setk(float4& v, int k, float val) {
    switch (k) { case 0: v.x = val; break; case 1: v.y = val; break;
                 case 2: v.z = val; break; default: v.w = val; }
}

struct St { float4 c, ym, yp, zm, zp; float xm, xp; };

__device__ __forceinline__ St gather(const float* __restrict__ f, int z, int y, int x4) {
    St s;
    const float4* f4 = (const float4*)f;
    s.c  = f4[(z*HH + y)*W4N + x4];
    s.ym = (y > 0)    ? f4[(z*HH + y-1)*W4N + x4]   : make_float4(0,0,0,0);
    s.yp = (y < HH-1) ? f4[(z*HH + y+1)*W4N + x4]   : make_float4(0,0,0,0);
    s.zm = (z > 0)    ? f4[((z-1)*HH + y)*W4N + x4] : make_float4(0,0,0,0);
    s.zp = (z < DD-1) ? f4[((z+1)*HH + y)*W4N + x4] : make_float4(0,0,0,0);
    int base = (z*HH + y)*WW + 4*x4;
    s.xm = (x4 > 0)     ? f[base - 1] : 0.0f;
    s.xp = (x4 < W4N-1) ? f[base + 4] : 0.0f;
    return s;
}

#define NBRS(sf, k, fc, fxm, fxp, fym, fyp, fzm, fzp)                       \
    float fc  = g((sf).c, k);                                               \
    float fxm = (k)     ? g((sf).c, (k)-1) : (sf).xm;                       \
    float fxp = ((k)<3) ? g((sf).c, (k)+1) : (sf).xp;                       \
    float fym = g((sf).ym, k), fyp = g((sf).yp, k);                         \
    float fzm = g((sf).zm, k), fzp = g((sf).zp, k);

// W1 prolongation fetch (zero outside domain)
__device__ __forceinline__ float wmat(const float* __restrict__ w1, int z, int y, int x) {
    if ((unsigned)z >= (unsigned)DD || (unsigned)y >= (unsigned)HH || (unsigned)x >= (unsigned)WW)
        return 0.0f;
    return w1[((z>>1)*(HH/2) + (y>>1))*(WW/2) + (x>>1)];
}

// ---------------- stage 0: INV = 1/(1+dt*sigma) ----------------
__global__ __launch_bounds__(256) void k_inv(const float4* __restrict__ sg) {
    int i = blockIdx.x*blockDim.x + threadIdx.x;
    if (i >= NQ) return;
    float4 s = sg[i];
    float4 inv;
    inv.x = 1.0f/(1.0f + DT*s.x);
    inv.y = 1.0f/(1.0f + DT*s.y);
    inv.z = 1.0f/(1.0f + DT*s.z);
    inv.w = 1.0f/(1.0f + DT*s.w);
    g_INV4[i] = inv;
}

// ============ fused momentum kernel: predictor + corrector in smem ============
// tile 32x8 in (x,y), z-chunk of 24, halo-2 input planes, halo-1 B planes.
#define TX 32
#define TY 8
#define ZCH 24
#define SIW 36                    // TX+4
#define SIH 12                    // TY+4
#define SIN (SIW*SIH)             // 432
#define SBW 34                    // TX+2
#define SBH 10                    // TY+2
#define SBN (SBW*SBH)             // 340

__global__ __launch_bounds__(256) void k_mom(const float* __restrict__ vu,
                                             const float* __restrict__ vv,
                                             const float* __restrict__ vw,
                                             const float* __restrict__ vp) {
    __shared__ float sUd[4][SIN], sVd[4][SIN], sWd[4][SIN], sP[4][SIN], sIV[4][SIN];
    __shared__ float sBU[3][SBN], sBV[3][SBN], sBW[3][SBN];

    const float* INV = (const float*)g_INV4;
    float* OU = (float*)g_U4; float* OV = (float*)g_V4; float* OW = (float*)g_W4;

    int tid = threadIdx.x;
    int gx0 = blockIdx.x * TX, gy0 = blockIdx.y * TY;
    int z0  = blockIdx.z * ZCH;

    // ---- plane loader: damped velocities + p + inv, zero outside domain ----
    auto load_in = [&](int gz) {
        int s = (gz + 4) & 3;
        bool zok = (unsigned)gz < (unsigned)DD;
        for (int idx = tid; idx < SIN; idx += 256) {
            int sy = idx / SIW, sx = idx - sy*SIW;
            int gy = gy0 - 2 + sy, gx = gx0 - 2 + sx;
            float u=0.f, v=0.f, w=0.f, p=0.f, iv=0.f;
            if (zok && (unsigned)gy < (unsigned)HH && (unsigned)gx < (unsigned)WW) {
                int i = (gz*HH + gy)*WW + gx;
                iv = INV[i];
                u = vu[i]*iv; v = vv[i]*iv; w = vw[i]*iv; p = vp[i];
            }
            sUd[s][idx]=u; sVd[s][idx]=v; sWd[s][idx]=w; sP[s][idx]=p; sIV[s][idx]=iv;
        }
    };

    // ---- B-plane compute (predictor) at global plane gz ----
    auto comp_B = [&](int gz) {
        int bs = (gz + 3) % 3;
        bool zok = (unsigned)gz < (unsigned)DD;
        int s_m = (gz + 3) & 3, s_c = (gz + 4) & 3, s_p = (gz + 5) & 3;
        for (int idx = tid; idx < SBN; idx += 256) {
            int sy = idx / SBW, sx = idx - sy*SBW;
            int gy = gy0 - 1 + sy, gx = gx0 - 1 + sx;
            float bu=0.f, bv=0.f, bw=0.f;
            if (zok && (unsigned)gy < (unsigned)HH && (unsigned)gx < (unsigned)WW) {
                int ic = (sy+1)*SIW + (sx+1);
                int nout = (gx==0)+(gx==WW-1)+(gy==0)+(gy==HH-1)+(gz==0)+(gz==DD-1);
                float hn = 0.5f * (float)nout;
                float invc = sIV[s_c][ic];

                float uc = sUd[s_c][ic];
                float uxm = sUd[s_c][ic-1],   uxp = sUd[s_c][ic+1];
                float uym = sUd[s_c][ic-SIW], uyp = sUd[s_c][ic+SIW];
                float uzm = sUd[s_m][ic],     uzp = sUd[s_p][ic];
                float vc = sVd[s_c][ic];
                float vxm = sVd[s_c][ic-1],   vxp = sVd[s_c][ic+1];
                float vym = sVd[s_c][ic-SIW], vyp = sVd[s_c][ic+SIW];
                float vzm = sVd[s_m][ic],     vzp = sVd[s_p][ic];
                float wc = sWd[s_c][ic];
                float wxm = sWd[s_c][ic-1],   wxp = sWd[s_c][ic+1];
                float wym = sWd[s_c][ic-SIW], wyp = sWd[s_c][ic+SIW];
                float wzm = sWd[s_m][ic],     wzp = sWd[s_p][ic];
                float pxm = sP[s_c][ic-1],    pxp = sP[s_c][ic+1];
                float pym = sP[s_c][ic-SIW],  pyp = sP[s_c][ic+SIW];
                float pzm = sP[s_m][ic],      pzp = sP[s_p][ic];

                float ku = (uxm+uxp+uym+uyp+uzm+uzp - 6.0f*uc) + hn*uc;
                float kv = (vxm+vxp+vym+vyp+vzm+vzp - 6.0f*vc) + hn*vc;
                float kw = (wxm+wxp+wym+wyp+wzm+wzp - 6.0f*wc) + hn*wc;

                float dxu = 0.5f*(uxp-uxm), dyu = 0.5f*(uyp-uym), dzu = 0.5f*(uzp-uzm);
                float dxv = 0.5f*(vxp-vxm), dyv = 0.5f*(vyp-vym), dzv = 0.5f*(vzp-vzm);
                float dxw = 0.5f*(wxp-wxm), dyw = 0.5f*(wyp-wym), dzw = 0.5f*(wzp-wzm);
                float dxp = 0.5f*(pxp-pxm), dyp = 0.5f*(pyp-pym), dzp = 0.5f*(pzp-pzm);

                bu = (uc + 0.5f*(RE*ku*DT - uc*dxu*DT - vc*dyu*DT - wc*dzu*DT) - dxp*DT) * invc;
                bv = (vc + 0.5f*(RE*kv*DT - uc*dxv*DT - vc*dyv*DT - wc*dzv*DT) - dyp*DT) * invc;
                bw = (wc + 0.5f*(RE*kw*DT - uc*dxw*DT - vc*dyw*DT - wc*dzw*DT) - dzp*DT) * invc;
            }
            sBU[bs][idx]=bu; sBV[bs][idx]=bv; sBW[bs][idx]=bw;
        }
    };

    // ---- prologue ----
    load_in(z0-2); load_in(z0-1); load_in(z0); load_in(z0+1);
    __syncthreads();
    comp_B(z0-1); comp_B(z0);

    int lx = tid & 31, ly = tid >> 5;
    int gx = gx0 + lx, gy = gy0 + ly;
    int ic = (ly+2)*SIW + (lx+2);
    int bcc = (ly+1)*SBW + (lx+1);

    for (int z = z0; z < z0 + ZCH; z++) {
        __syncthreads();
        load_in(z+2);
        __syncthreads();
        comp_B(z+1);
        __syncthreads();

        // ---- corrector (stage3) at plane z ----
        int s_m = (z + 3) & 3, s_c = (z + 4) & 3, s_p = (z + 5) & 3;
        int bm = (z + 2) % 3, bc = z % 3, bp = (z + 1) % 3;

        int nout = (gx==0)+(gx==WW-1)+(gy==0)+(gy==HH-1)+(z==0)+(z==DD-1);
        float hn = 0.5f * (float)nout;
        float invc = sIV[s_c][ic];
        float uc = sUd[s_c][ic], vc = sVd[s_c][ic], wc = sWd[s_c][ic];

        float buc = sBU[bc][bcc];
        float buxm = sBU[bc][bcc-1],   buxp = sBU[bc][bcc+1];
        float buym = sBU[bc][bcc-SBW], buyp = sBU[bc][bcc+SBW];
        float buzm = sBU[bm][bcc],     buzp = sBU[bp][bcc];
        float bvc = sBV[bc][bcc];
        float bvxm = sBV[bc][bcc-1],   bvxp = sBV[bc][bcc+1];
        float bvym = sBV[bc][bcc-SBW], bvyp = sBV[bc][bcc+SBW];
        float bvzm = sBV[bm][bcc],     bvzp = sBV[bp][bcc];
        float bwc = sBW[bc][bcc];
        float bwxm = sBW[bc][bcc-1],   bwxp = sBW[bc][bcc+1];
        float bwym = sBW[bc][bcc-SBW], bwyp = sBW[bc][bcc+SBW];
        float bwzm = sBW[bm][bcc],     bwzp = sBW[bp][bcc];

        float pxm = sP[s_c][ic-1],   pxp = sP[s_c][ic+1];
        float pym = sP[s_c][ic-SIW], pyp = sP[s_c][ic+SIW];
        float pzm = sP[s_m][ic],     pzp = sP[s_p][ic];

        float kub = (buxm+buxp+buym+buyp+buzm+buzp - 6.0f*buc) + hn*buc;
        float kvb = (bvxm+bvxp+bvym+bvyp+bvzm+bvzp - 6.0f*bvc) + hn*bvc;
        float kwb = (bwxm+bwxp+bwym+bwyp+bwzm+bwzp - 6.0f*bwc) + hn*bwc;

        float dx_bu=0.5f*(buxp-buxm), dy_bu=0.5f*(buyp-buym), dz_bu=0.5f*(buzp-buzm);
        float dx_bv=0.5f*(bvxp-bvxm), dy_bv=0.5f*(bvyp-bvym), dz_bv=0.5f*(bvzp-bvzm);
        float dx_bw=0.5f*(bwxp-bwxm), dy_bw=0.5f*(bwyp-bwym), dz_bw=0.5f*(bwzp-bwzm);
        float dxp = 0.5f*(pxp-pxm), dyp = 0.5f*(pyp-pym), dzp = 0.5f*(pzp-pzm);

        int i = (z*HH + gy)*WW + gx;
        OU[i] = (uc + RE*kub*DT - buc*dx_bu*DT - bvc*dy_bu*DT - bwc*dz_bu*DT - dxp*DT) * invc;
        OV[i] = (vc + RE*kvb*DT - buc*dx_bv*DT - bvc*dy_bv*DT - bwc*dz_bv*DT - dyp*DT) * invc;
        OW[i] = (wc + RE*kwb*DT - buc*dx_bw*DT - bvc*dy_bw*DT - bwc*dz_bw*DT - dzp*DT) * invc;
    }
}

// ---------------- fused rhs + fine residual (iter 1) [R4 form] ----------------
__global__ __launch_bounds__(192) void k_residb(const float* __restrict__ vp) {
    const float* U = (const float*)g_U4;
    const float* V = (const float*)g_V4;
    const float* W = (const float*)g_W4;
    int x4 = threadIdx.x, y = blockIdx.x*4 + threadIdx.y, z = blockIdx.y;
    int i4 = (z*HH + y)*W4N + x4;

    float4 ucv = ((const float4*)U)[i4];
    int base = (z*HH + y)*WW + 4*x4;
    float uxm_s = (x4 > 0)     ? U[base - 1] : 0.0f;
    float uxp_s = (x4 < W4N-1) ? U[base + 4] : 0.0f;

    const float4* V4 = (const float4*)V;
    float4 vym = (y > 0)    ? V4[(z*HH + y-1)*W4N + x4] : make_float4(0,0,0,0);
    float4 vyp = (y < HH-1) ? V4[(z*HH + y+1)*W4N + x4] : make_float4(0,0,0,0);

    const float4* Wp4 = (const float4*)W;
    float4 wzm = (z > 0)    ? Wp4[((z-1)*HH + y)*W4N + x4] : make_float4(0,0,0,0);
    float4 wzp = (z < DD-1) ? Wp4[((z+1)*HH + y)*W4N + x4] : make_float4(0,0,0,0);

    St sp = gather(vp, z, y, x4);

    float4 b4, r4;
#pragma unroll
    for (int k = 0; k < 4; k++) {
        float uxm = k ? g(ucv,k-1) : uxm_s;
        float uxp = (k<3) ? g(ucv,k+1) : uxp_s;
        float dxu = 0.5f*(uxp - uxm);
        float dyv = 0.5f*(g(vyp,k) - g(vym,k));
        float dzw = 0.5f*(g(wzp,k) - g(wzm,k));
        float b = -(dxu + dyv + dzw) * (1.0f/DT);

        NBRS(sp, k, pc, pxm, pxp, pym, pyp, pzm, pzp);
        float lap = pxm+pxp+pym+pyp+pzm+pzp - 6.0f*pc;
        setk(b4, k, b);
        setk(r4, k, lap - b);
    }
    g_B4[i4] = b4;
    g_R04[i4] = r4;
}

// ---------------- fused 3-level restriction: R0->R1,R2,R3 in one pass ----------------
__global__ __launch_bounds__(64) void k_restrict3(const float* __restrict__ src) {
    int cell = blockIdx.x;
    int x3 = cell % 24, t = cell / 24, y3 = t % 24, z3 = t / 24;
    int tid = threadIdx.x;
    int x1 = tid & 3, y1 = (tid >> 2) & 3, z1 = tid >> 4;

    int fz = z3*8 + z1*2, fy = y3*8 + y1*2, fx = x3*8 + x1*2;
    const float* s = src + ((size_t)fz*HH + fy)*WW + fx;
    float2 a0 = *(const float2*)(s);
    float2 a1 = *(const float2*)(s + WW);
    float2 a2 = *(const float2*)(s + HH*WW);
    float2 a3 = *(const float2*)(s + HH*WW + WW);
    float r1 = 0.125f*(a0.x+a0.y+a1.x+a1.y+a2.x+a2.y+a3.x+a3.y);
    g_R1[((z3*4+z1)*96 + (y3*4+y1))*96 + (x3*4+x1)] = r1;

    __shared__ float sm1[64];
    __shared__ float sm2[8];
    sm1[tid] = r1;
    __syncthreads();
    if (tid < 8) {
        int x2 = tid & 1, y2 = (tid >> 1) & 1, z2 = tid >> 2;
        float r2 = 0.0f;
#pragma unroll
        for (int dz = 0; dz < 2; dz++)
#pragma unroll
            for (int dy = 0; dy < 2; dy++)
#pragma unroll
                for (int dx = 0; dx < 2; dx++)
                    r2 += sm1[((2*z2+dz)<<4) | ((2*y2+dy)<<2) | (2*x2+dx)];
        r2 *= 0.125f;
        g_R2[((z3*2+z2)*48 + (y3*2+y2))*48 + (x3*2+x2)] = r2;
        sm2[tid] = r2;
    }
    __syncthreads();
    if (tid == 0) {
        float r3 = 0.0f;
#pragma unroll
        for (int j = 0; j < 8; j++) r3 += sm2[j];
        g_R3[(z3*24 + y3)*24 + x3] = 0.125f * r3;
    }
}

// ---- prolong(coarse)*cscale then Jacobi smooth: out = w - A0(w)/diag + r/diag ----
__global__ void k_smooth(const float* __restrict__ coarse, const float* __restrict__ r,
                         float* __restrict__ out, int dz, int dy, int dx, float cscale) {
    int i = blockIdx.x*blockDim.x + threadIdx.x;
    int n = dz*dy*dx;
    if (i >= n) return;
    int x = i % dx, t = i / dx, y = t % dy, z = t / dy;
    int cy = dy >> 1, cx = dx >> 1;
    auto wp = [&](int zz, int yy, int xx) -> float {
        if ((unsigned)zz >= (unsigned)dz || (unsigned)yy >= (unsigned)dy || (unsigned)xx >= (unsigned)dx)
            return 0.0f;
        return cscale * coarse[((zz>>1)*cy + (yy>>1))*cx + (xx>>1)];
    };
    float c = wp(z,y,x);
    float a = wp(z,y,x-1)+wp(z,y,x+1)+wp(z,y-1,x)+wp(z,y+1,x)+wp(z-1,y,x)+wp(z+1,y,x) - 6.0f*c;
    out[i] = c - a*INVD + r[i]*INVD;
}

// -------- fused iter-1 p-update + iter-2 residual [R4 form] ----------------
__global__ __launch_bounds__(192) void k_pup_resid(const float* __restrict__ vp) {
    const float* R0 = (const float*)g_R04;
    int x4 = threadIdx.x, y = blockIdx.x*4 + threadIdx.y, z = blockIdx.y;
    int i4 = (z*HH + y)*W4N + x4;

    St sp = gather(vp, z, y, x4);
    St sr = gather(R0, z, y, x4);
    float4 b4 = g_B4[i4];

    float4 p4, r4;
#pragma unroll
    for (int k = 0; k < 4; k++) {
        int x = 4*x4 + k;
        NBRS(sp, k, pc, pxm, pxp, pym, pyp, pzm, pzp);
        NBRS(sr, k, rc, rxm, rxp, rym, ryp, rzm, rzp);

        float p1c  = pc  - wmat(g_W1, z, y, x)   - rc  * INVD;
        float p1xm = pxm - wmat(g_W1, z, y, x-1) - rxm * INVD;
        float p1xp = pxp - wmat(g_W1, z, y, x+1) - rxp * INVD;
        float p1ym = pym - wmat(g_W1, z, y-1, x) - rym * INVD;
        float p1yp = pyp - wmat(g_W1, z, y+1, x) - ryp * INVD;
        float p1zm = pzm - wmat(g_W1, z-1, y, x) - rzm * INVD;
        float p1zp = pzp - wmat(g_W1, z+1, y, x) - rzp * INVD;

        float lap = p1xm+p1xp+p1ym+p1yp+p1zm+p1zp - 6.0f*p1c;
        setk(p4, k, p1c);
        setk(r4, k, lap - g(b4, k));
    }
    g_P4[i4] = p4;
    g_R0b4[i4] = r4;
}

// -------- fused iter-2 p-update + final projection + sb [R4 form] --------
__global__ __launch_bounds__(192) void k_pfinal(float* __restrict__ out_p, float* __restrict__ out_wmg,
                                                float* __restrict__ ou, float* __restrict__ ov,
                                                float* __restrict__ ow) {
    const float* P  = (const float*)g_P4;
    const float* R0 = (const float*)g_R0b4;
    int x4 = threadIdx.x, y = blockIdx.x*4 + threadIdx.y, z = blockIdx.y;
    int i4 = (z*HH + y)*W4N + x4;

    St sp = gather(P, z, y, x4);
    St sr = gather(R0, z, y, x4);
    float4 u4 = g_U4[i4], v4 = g_V4[i4], w4 = g_W4[i4], inv4 = g_INV4[i4];

    float4 op4, owm4, ou4, ov4, ow4;
#pragma unroll
    for (int k = 0; k < 4; k++) {
        int x = 4*x4 + k;
        NBRS(sp, k, pc, pxm, pxp, pym, pyp, pzm, pzp);
        NBRS(sr, k, rc, rxm, rxp, rym, ryp, rzm, rzp);

        float wm   = wmat(g_W1, z, y, x);
        float p2c  = pc  - wm                    - rc  * INVD;
        float p2xm = pxm - wmat(g_W1, z, y, x-1) - rxm * INVD;
        float p2xp = pxp - wmat(g_W1, z, y, x+1) - rxp * INVD;
        float p2ym = pym - wmat(g_W1, z, y-1, x) - rym * INVD;
        float p2yp = pyp - wmat(g_W1, z, y+1, x) - ryp * INVD;
        float p2zm = pzm - wmat(g_W1, z-1, y, x) - rzm * INVD;
        float p2zp = pzp - wmat(g_W1, z+1, y, x) - rzp * INVD;

        float dxp = 0.5f*(p2xp - p2xm);
        float dyp = 0.5f*(p2yp - p2ym);
        float dzp = 0.5f*(p2zp - p2zm);

        float invc = g(inv4, k);
        setk(op4, k, p2c);
        setk(owm4, k, wm);
        setk(ou4, k, (g(u4,k) - dxp*DT) * invc);
        setk(ov4, k, (g(v4,k) - dyp*DT) * invc);
        setk(ow4, k, (g(w4,k) - dzp*DT) * invc);
    }
    ((float4*)out_p)[i4]   = op4;
    ((float4*)out_wmg)[i4] = owm4;
    ((float4*)ou)[i4] = ou4;
    ((float4*)ov)[i4] = ov4;
    ((float4*)ow)[i4] = ow4;
}

// ---------------- launch ----------------
extern "C" void kernel_launch(void* const* d_in, const int* in_sizes, int n_in,
                              void* d_out, int out_size) {
    const float* vu = (const float*)d_in[0];
    const float* vv = (const float*)d_in[1];
    const float* vw = (const float*)d_in[2];
    const float* vp = (const float*)d_in[3];
    const float* sg = (const float*)d_in[4];

    float* out     = (float*)d_out;
    float* out_u   = out;
    float* out_v   = out + (size_t)NFULL;
    float* out_w   = out + (size_t)2*NFULL;
    float* out_p   = out + (size_t)3*NFULL;
    float* out_wmg = out + (size_t)4*NFULL;
    float* out_r   = out + (size_t)5*NFULL;

    void *pR0, *pR0b, *pR1, *pR2, *pR3, *pW2, *pW1;
    cudaGetSymbolAddress(&pR0,  g_R04);
    cudaGetSymbolAddress(&pR0b, g_R0b4);
    cudaGetSymbolAddress(&pR1,  g_R1);
    cudaGetSymbolAddress(&pR2,  g_R2);
    cudaGetSymbolAddress(&pR3,  g_R3);
    cudaGetSymbolAddress(&pW2,  g_W2);
    cudaGetSymbolAddress(&pW1,  g_W1);

    dim3 blk(W4N, 4, 1);          // 192 threads
    dim3 grd(HH/4, DD);
    dim3 blkM(256, 1, 1);
    dim3 grdM(WW/TX, HH/TY, DD/ZCH);   // (6, 24, 4)

    k_inv<<<(NQ+255)/256, 256>>>((const float4*)sg);
    k_mom<<<grdM, blkM>>>(vu, vv, vw, vp);

    // ---- MG iteration 1 (p = vp) ----
    k_residb<<<grd, blk>>>(vp);
    k_restrict3<<<NL3, 64>>>((const float*)pR0);
    k_smooth<<<(NL2+255)/256, 256>>>((const float*)pR3, (const float*)pR2, (float*)pW2,
                                     24, 48, 48, INVD);
    k_smooth<<<(NL1+255)/256, 256>>>((const float*)pW2, (const float*)pR1, (float*)pW1,
                                     48, 96, 96, 1.0f);

    // ---- fused: P = p1; R0b = A(p1) - b ----
    k_pup_resid<<<grd, blk>>>(vp);

    // ---- MG iteration 2 coarse solve ----
    k_restrict3<<<NL3, 64>>>((const float*)pR0b);
    k_smooth<<<(NL2+255)/256, 256>>>((const float*)pR3, (const float*)pR2, (float*)pW2,
                                     24, 48, 48, INVD);
    k_smooth<<<(NL1+255)/256, 256>>>((const float*)pW2, (const float*)pR1, (float*)pW1,
                                     48, 96, 96, 1.0f);

    k_pfinal<<<grd, blk>>>(out_p, out_wmg, out_u, out_v, out_w);
    cudaMemcpyAsync(out_r, pR3, NL3*sizeof(float), cudaMemcpyDeviceToDevice);
}

// round 7
// speedup vs baseline: 1.0840x; 1.0615x over previous
#include <cuda_runtime.h>

#define DD 96
#define HH 192
#define WW 192
#define W4N (WW/4)                // 48
#define X8N (WW/8)                // 24
#define NFULL (DD*HH*WW)          // 3538944
#define NQ    (NFULL/4)
#define NL1 (48*96*96)            // 442368
#define NL2 (24*48*48)            // 55296
#define NL3 (12*24*24)            // 6912

#define DT   0.01f
#define RE   0.001f
#define INVD (-1.0f/6.0f)         // 1/diag, diag = -6

// ---------------- scratch (device globals, float4-aligned) ----------------
__device__ float4 g_U4[NQ], g_V4[NQ], g_W4[NQ], g_INV4[NQ];
__device__ float4 g_BU4[NQ], g_BV4[NQ], g_BW4[NQ];
__device__ float4 g_R04[NQ], g_R0b4[NQ], g_P4[NQ];
__device__ float g_R1[NL1], g_R2[NL2], g_R3[NL3];
__device__ float g_W2[NL2], g_W1[NL1];

// ---------------- helpers ----------------
__device__ __forceinline__ float g(const float4 v, int k) {
    switch (k) { case 0: return v.x; case 1: return v.y; case 2: return v.z; default: return v.w; }
}
__device__ __forceinline__ void setk(float4& v, int k, float val) {
    switch (k) { case 0: v.x = val; break; case 1: v.y = val; break;
                 case 2: v.z = val; break; default: v.w = val; }
}

struct St { float4 c, ym, yp, zm, zp; float xm, xp; };

__device__ __forceinline__ St gather(const float* __restrict__ f, int z, int y, int x4) {
    St s;
    const float4* f4 = (const float4*)f;
    s.c  = f4[(z*HH + y)*W4N + x4];
    s.ym = (y > 0)    ? f4[(z*HH + y-1)*W4N + x4]   : make_float4(0,0,0,0);
    s.yp = (y < HH-1) ? f4[(z*HH + y+1)*W4N + x4]   : make_float4(0,0,0,0);
    s.zm = (z > 0)    ? f4[((z-1)*HH + y)*W4N + x4] : make_float4(0,0,0,0);
    s.zp = (z < DD-1) ? f4[((z+1)*HH + y)*W4N + x4] : make_float4(0,0,0,0);
    int base = (z*HH + y)*WW + 4*x4;
    s.xm = (x4 > 0)     ? f[base - 1] : 0.0f;
    s.xp = (x4 < W4N-1) ? f[base + 4] : 0.0f;
    return s;
}

__device__ __forceinline__ void damp(St& a, const St& s) {
    a.c.x*=s.c.x;   a.c.y*=s.c.y;   a.c.z*=s.c.z;   a.c.w*=s.c.w;
    a.ym.x*=s.ym.x; a.ym.y*=s.ym.y; a.ym.z*=s.ym.z; a.ym.w*=s.ym.w;
    a.yp.x*=s.yp.x; a.yp.y*=s.yp.y; a.yp.z*=s.yp.z; a.yp.w*=s.yp.w;
    a.zm.x*=s.zm.x; a.zm.y*=s.zm.y; a.zm.z*=s.zm.z; a.zm.w*=s.zm.w;
    a.zp.x*=s.zp.x; a.zp.y*=s.zp.y; a.zp.z*=s.zp.z; a.zp.w*=s.zp.w;
    a.xm*=s.xm;     a.xp*=s.xp;
}

#define NBRS(sf, k, fc, fxm, fxp, fym, fyp, fzm, fzp)                       \
    float fc  = g((sf).c, k);                                               \
    float fxm = (k)     ? g((sf).c, (k)-1) : (sf).xm;                       \
    float fxp = ((k)<3) ? g((sf).c, (k)+1) : (sf).xp;                       \
    float fym = g((sf).ym, k), fyp = g((sf).yp, k);                         \
    float fzm = g((sf).zm, k), fzp = g((sf).zp, k);

#define SPREAD8(dst, a, b) { dst[0]=(a).x; dst[1]=(a).y; dst[2]=(a).z; dst[3]=(a).w; \
                             dst[4]=(b).x; dst[5]=(b).y; dst[6]=(b).z; dst[7]=(b).w; }
#define SPREAD10(dst, s0, a, b, s1) { dst[0]=(s0); dst[1]=(a).x; dst[2]=(a).y; dst[3]=(a).z; \
                                      dst[4]=(a).w; dst[5]=(b).x; dst[6]=(b).y; dst[7]=(b).z; \
                                      dst[8]=(b).w; dst[9]=(s1); }

// W1 prolongation fetch (zero outside domain)
__device__ __forceinline__ float wmat(const float* __restrict__ w1, int z, int y, int x) {
    if ((unsigned)z >= (unsigned)DD || (unsigned)y >= (unsigned)HH || (unsigned)x >= (unsigned)WW)
        return 0.0f;
    return w1[((z>>1)*(HH/2) + (y>>1))*(WW/2) + (x>>1)];
}

// ---------------- stage 0: INV = 1/(1+dt*sigma) ----------------
__global__ __launch_bounds__(256) void k_inv(const float4* __restrict__ sg) {
    int i = blockIdx.x*blockDim.x + threadIdx.x;
    if (i >= NQ) return;
    float4 s = sg[i];
    float4 inv;
    inv.x = 1.0f/(1.0f + DT*s.x);
    inv.y = 1.0f/(1.0f + DT*s.y);
    inv.z = 1.0f/(1.0f + DT*s.z);
    inv.w = 1.0f/(1.0f + DT*s.w);
    g_INV4[i] = inv;
}

// ---------------- predictor: BU/BV/BW [R4 form] ----------------
__global__ __launch_bounds__(192) void k_pred(const float* __restrict__ vu,
                                              const float* __restrict__ vv,
                                              const float* __restrict__ vw,
                                              const float* __restrict__ vp) {
    const float* INV = (const float*)g_INV4;
    int x4 = threadIdx.x, y = blockIdx.x*4 + threadIdx.y, z = blockIdx.y;

    St si = gather(INV, z, y, x4);
    St su = gather(vu, z, y, x4); damp(su, si);
    St sv = gather(vv, z, y, x4); damp(sv, si);
    St sw = gather(vw, z, y, x4); damp(sw, si);
    St sp = gather(vp, z, y, x4);

    float4 bu4, bv4, bw4;
#pragma unroll
    for (int k = 0; k < 4; k++) {
        int x = 4*x4 + k;
        int nout = (x==0)+(x==WW-1)+(y==0)+(y==HH-1)+(z==0)+(z==DD-1);
        float hn = 0.5f * (float)nout;
        float invc = g(si.c, k);

        NBRS(su, k, uc, uxm, uxp, uym, uyp, uzm, uzp);
        NBRS(sv, k, vc, vxm, vxp, vym, vyp, vzm, vzp);
        NBRS(sw, k, wc, wxm, wxp, wym, wyp, wzm, wzp);
        NBRS(sp, k, pc, pxm, pxp, pym, pyp, pzm, pzp);
        (void)pc;

        float dxp = 0.5f*(pxp-pxm), dyp = 0.5f*(pyp-pym), dzp = 0.5f*(pzp-pzm);

        float ku = (uxm+uxp+uym+uyp+uzm+uzp - 6.0f*uc) + hn*uc;
        float kv = (vxm+vxp+vym+vyp+vzm+vzp - 6.0f*vc) + hn*vc;
        float kw = (wxm+wxp+wym+wyp+wzm+wzp - 6.0f*wc) + hn*wc;

        float dxu = 0.5f*(uxp-uxm), dyu = 0.5f*(uyp-uym), dzu = 0.5f*(uzp-uzm);
        float dxv = 0.5f*(vxp-vxm), dyv = 0.5f*(vyp-vym), dzv = 0.5f*(vzp-vzm);
        float dxw = 0.5f*(wxp-wxm), dyw = 0.5f*(wyp-wym), dzw = 0.5f*(wzp-wzm);

        setk(bu4, k, (uc + 0.5f*(RE*ku*DT - uc*dxu*DT - vc*dyu*DT - wc*dzu*DT) - dxp*DT) * invc);
        setk(bv4, k, (vc + 0.5f*(RE*kv*DT - uc*dxv*DT - vc*dyv*DT - wc*dzv*DT) - dyp*DT) * invc);
        setk(bw4, k, (wc + 0.5f*(RE*kw*DT - uc*dxw*DT - vc*dyw*DT - wc*dzw*DT) - dzp*DT) * invc);
    }
    int i4 = (z*HH + y)*W4N + x4;
    g_BU4[i4] = bu4; g_BV4[i4] = bv4; g_BW4[i4] = bw4;
}

// ---------------- corrector: write U,V,W [R4 form] ----------------
__global__ __launch_bounds__(192) void k_stage3(const float* __restrict__ vu,
                                                const float* __restrict__ vv,
                                                const float* __restrict__ vw,
                                                const float* __restrict__ vp) {
    const float* BU = (const float*)g_BU4;
    const float* BV = (const float*)g_BV4;
    const float* BW = (const float*)g_BW4;
    int x4 = threadIdx.x, y = blockIdx.x*4 + threadIdx.y, z = blockIdx.y;
    int i4 = (z*HH + y)*W4N + x4;

    St sbu = gather(BU, z, y, x4);
    St sbv = gather(BV, z, y, x4);
    St sbw = gather(BW, z, y, x4);
    St sp  = gather(vp, z, y, x4);

    float4 inv4 = g_INV4[i4];
    float4 u0 = ((const float4*)vu)[i4];
    float4 v0 = ((const float4*)vv)[i4];
    float4 w0 = ((const float4*)vw)[i4];

    float4 un4, vn4, wn4;
#pragma unroll
    for (int k = 0; k < 4; k++) {
        int x = 4*x4 + k;
        int nout = (x==0)+(x==WW-1)+(y==0)+(y==HH-1)+(z==0)+(z==DD-1);
        float hn = 0.5f * (float)nout;
        float invc = g(inv4, k);
        float uc = g(u0,k)*invc, vc = g(v0,k)*invc, wc = g(w0,k)*invc;

        NBRS(sbu, k, buc, buxm, buxp, buym, buyp, buzm, buzp);
        NBRS(sbv, k, bvc, bvxm, bvxp, bvym, bvyp, bvzm, bvzp);
        NBRS(sbw, k, bwc, bwxm, bwxp, bwym, bwyp, bwzm, bwzp);
        NBRS(sp,  k, pc,  pxm,  pxp,  pym,  pyp,  pzm,  pzp);
        (void)pc;

        float dxp = 0.5f*(pxp-pxm), dyp = 0.5f*(pyp-pym), dzp = 0.5f*(pzp-pzm);

        float kub = (buxm+buxp+buym+buyp+buzm+buzp - 6.0f*buc) + hn*buc;
        float kvb = (bvxm+bvxp+bvym+bvyp+bvzm+bvzp - 6.0f*bvc) + hn*bvc;
        float kwb = (bwxm+bwxp+bwym+bwyp+bwzm+bwzp - 6.0f*bwc) + hn*bwc;

        float dx_bu=0.5f*(buxp-buxm), dy_bu=0.5f*(buyp-buym), dz_bu=0.5f*(buzp-buzm);
        float dx_bv=0.5f*(bvxp-bvxm), dy_bv=0.5f*(bvyp-bvym), dz_bv=0.5f*(bvzp-bvzm);
        float dx_bw=0.5f*(bwxp-bwxm), dy_bw=0.5f*(bwyp-bwym), dz_bw=0.5f*(bwzp-bwzm);

        setk(un4, k, (uc + RE*kub*DT - buc*dx_bu*DT - bvc*dy_bu*DT - bwc*dz_bu*DT - dxp*DT) * invc);
        setk(vn4, k, (vc + RE*kvb*DT - buc*dx_bv*DT - bvc*dy_bv*DT - bwc*dz_bv*DT - dyp*DT) * invc);
        setk(wn4, k, (wc + RE*kwb*DT - buc*dx_bw*DT - bvc*dy_bw*DT - bwc*dz_bw*DT - dzp*DT) * invc);
    }
    g_U4[i4] = un4; g_V4[i4] = vn4; g_W4[i4] = wn4;
}

// ------- fine residual (iter 1), widened x8, no B store: r0 = lap(p) - b -------
__global__ __launch_bounds__(192) void k_residb(const float* __restrict__ vp) {
    const float* U = (const float*)g_U4;
    const float* V = (const float*)g_V4;
    const float* W = (const float*)g_W4;
    int q = threadIdx.x;                        // 0..23, covers x = 8q..8q+7
    int y = blockIdx.x*8 + threadIdx.y;         // blockDim.y = 8
    int z = blockIdx.y;
    int i4 = (z*HH + y)*W4N + 2*q;
    int base = (z*HH + y)*WW + 8*q;

    // U: x-neighbors only
    const float4* U4 = (const float4*)U;
    float4 u_c0 = U4[i4], u_c1 = U4[i4+1];
    float u_xm = (q > 0)     ? U[base - 1] : 0.0f;
    float u_xp = (q < X8N-1) ? U[base + 8] : 0.0f;

    // V: y-neighbors only
    const float4* V4 = (const float4*)V;
    float4 v_ym0 = make_float4(0,0,0,0), v_ym1 = v_ym0, v_yp0 = v_ym0, v_yp1 = v_ym0;
    if (y > 0)    { v_ym0 = V4[(z*HH + y-1)*W4N + 2*q]; v_ym1 = V4[(z*HH + y-1)*W4N + 2*q+1]; }
    if (y < HH-1) { v_yp0 = V4[(z*HH + y+1)*W4N + 2*q]; v_yp1 = V4[(z*HH + y+1)*W4N + 2*q+1]; }

    // W: z-neighbors only
    const float4* W4p = (const float4*)W;
    float4 w_zm0 = make_float4(0,0,0,0), w_zm1 = w_zm0, w_zp0 = w_zm0, w_zp1 = w_zm0;
    if (z > 0)    { w_zm0 = W4p[((z-1)*HH + y)*W4N + 2*q]; w_zm1 = W4p[((z-1)*HH + y)*W4N + 2*q+1]; }
    if (z < DD-1) { w_zp0 = W4p[((z+1)*HH + y)*W4N + 2*q]; w_zp1 = W4p[((z+1)*HH + y)*W4N + 2*q+1]; }

    // p: full stencil
    const float4* P4v = (const float4*)vp;
    float4 p_c0 = P4v[i4], p_c1 = P4v[i4+1];
    float p_xm = (q > 0)     ? vp[base - 1] : 0.0f;
    float p_xp = (q < X8N-1) ? vp[base + 8] : 0.0f;
    float4 p_ym0 = make_float4(0,0,0,0), p_ym1 = p_ym0, p_yp0 = p_ym0, p_yp1 = p_ym0;
    if (y > 0)    { p_ym0 = P4v[(z*HH + y-1)*W4N + 2*q]; p_ym1 = P4v[(z*HH + y-1)*W4N + 2*q+1]; }
    if (y < HH-1) { p_yp0 = P4v[(z*HH + y+1)*W4N + 2*q]; p_yp1 = P4v[(z*HH + y+1)*W4N + 2*q+1]; }
    float4 p_zm0 = make_float4(0,0,0,0), p_zm1 = p_zm0, p_zp0 = p_zm0, p_zp1 = p_zm0;
    if (z > 0)    { p_zm0 = P4v[((z-1)*HH + y)*W4N + 2*q]; p_zm1 = P4v[((z-1)*HH + y)*W4N + 2*q+1]; }
    if (z < DD-1) { p_zp0 = P4v[((z+1)*HH + y)*W4N + 2*q]; p_zp1 = P4v[((z+1)*HH + y)*W4N + 2*q+1]; }

    float ua[10], pa[10], vym[8], vyp[8], wzm[8], wzp[8], pym[8], pyp[8], pzm[8], pzp[8];
    SPREAD10(ua, u_xm, u_c0, u_c1, u_xp);
    SPREAD10(pa, p_xm, p_c0, p_c1, p_xp);
    SPREAD8(vym, v_ym0, v_ym1); SPREAD8(vyp, v_yp0, v_yp1);
    SPREAD8(wzm, w_zm0, w_zm1); SPREAD8(wzp, w_zp0, w_zp1);
    SPREAD8(pym, p_ym0, p_ym1); SPREAD8(pyp, p_yp0, p_yp1);
    SPREAD8(pzm, p_zm0, p_zm1); SPREAD8(pzp, p_zp0, p_zp1);

    float rr[8];
#pragma unroll
    for (int j = 0; j < 8; j++) {
        float dxu = 0.5f*(ua[j+2] - ua[j]);
        float dyv = 0.5f*(vyp[j] - vym[j]);
        float dzw = 0.5f*(wzp[j] - wzm[j]);
        float b = -(dxu + dyv + dzw) * (1.0f/DT);
        float lap = pa[j] + pa[j+2] + pym[j] + pyp[j] + pzm[j] + pzp[j] - 6.0f*pa[j+1];
        rr[j] = lap - b;
    }
    g_R04[i4]   = make_float4(rr[0], rr[1], rr[2], rr[3]);
    g_R04[i4+1] = make_float4(rr[4], rr[5], rr[6], rr[7]);
}

// ---------------- generic restriction (2x2x2 avg, stride 2) [R4 form] ----------------
__global__ void k_restrict(const float* __restrict__ src, float* __restrict__ dst,
                           int dz, int dy, int dx) {
    int i = blockIdx.x*blockDim.x + threadIdx.x;
    int n = dz*dy*dx;
    if (i >= n) return;
    int x = i % dx, t = i / dx, y = t % dy, z = t / dy;
    int sy = dy*2, sx = dx*2;
    const float* s = src + ((2*z)*sy + 2*y)*sx + 2*x;
    float sum = s[0] + s[1] + s[sx] + s[sx+1];
    const float* s2 = s + sy*sx;
    sum += s2[0] + s2[1] + s2[sx] + s2[sx+1];
    dst[i] = 0.125f * sum;
}

// ---- prolong(coarse)*cscale then Jacobi smooth [R4 form] ----
__global__ void k_smooth(const float* __restrict__ coarse, const float* __restrict__ r,
                         float* __restrict__ out, int dz, int dy, int dx, float cscale) {
    int i = blockIdx.x*blockDim.x + threadIdx.x;
    int n = dz*dy*dx;
    if (i >= n) return;
    int x = i % dx, t = i / dx, y = t % dy, z = t / dy;
    int cy = dy >> 1, cx = dx >> 1;
    auto wp = [&](int zz, int yy, int xx) -> float {
        if ((unsigned)zz >= (unsigned)dz || (unsigned)yy >= (unsigned)dy || (unsigned)xx >= (unsigned)dx)
            return 0.0f;
        return cscale * coarse[((zz>>1)*cy + (yy>>1))*cx + (xx>>1)];
    };
    float c = wp(z,y,x);
    float a = wp(z,y,x-1)+wp(z,y,x+1)+wp(z,y-1,x)+wp(z,y+1,x)+wp(z-1,y,x)+wp(z+1,y,x) - 6.0f*c;
    out[i] = c - a*INVD + r[i]*INVD;
}

// -------- fused iter-1 p-update + iter-2 residual (d-trick, widened x8) --------
// d = -prol(w1) - r0/diag ; P = p + d ; R0b = lap(d) + r0
__global__ __launch_bounds__(192) void k_pup_resid(const float* __restrict__ vp) {
    const float* R0 = (const float*)g_R04;
    int q = threadIdx.x;
    int y = blockIdx.x*8 + threadIdx.y;
    int z = blockIdx.y;
    int i4 = (z*HH + y)*W4N + 2*q;
    int base = (z*HH + y)*WW + 8*q;

    // r0 full stencil
    const float4* R4v = (const float4*)R0;
    float4 r_c0 = R4v[i4], r_c1 = R4v[i4+1];
    float r_xm = (q > 0)     ? R0[base - 1] : 0.0f;
    float r_xp = (q < X8N-1) ? R0[base + 8] : 0.0f;
    float4 r_ym0 = make_float4(0,0,0,0), r_ym1 = r_ym0, r_yp0 = r_ym0, r_yp1 = r_ym0;
    if (y > 0)    { r_ym0 = R4v[(z*HH + y-1)*W4N + 2*q]; r_ym1 = R4v[(z*HH + y-1)*W4N + 2*q+1]; }
    if (y < HH-1) { r_yp0 = R4v[(z*HH + y+1)*W4N + 2*q]; r_yp1 = R4v[(z*HH + y+1)*W4N + 2*q+1]; }
    float4 r_zm0 = make_float4(0,0,0,0), r_zm1 = r_zm0, r_zp0 = r_zm0, r_zp1 = r_zm0;
    if (z > 0)    { r_zm0 = R4v[((z-1)*HH + y)*W4N + 2*q]; r_zm1 = R4v[((z-1)*HH + y)*W4N + 2*q+1]; }
    if (z < DD-1) { r_zp0 = R4v[((z+1)*HH + y)*W4N + 2*q]; r_zp1 = R4v[((z+1)*HH + y)*W4N + 2*q+1]; }

    // p centers only
    float4 p_c0 = ((const float4*)vp)[i4], p_c1 = ((const float4*)vp)[i4+1];

    // W1 coarse-row caches
    int cz = z>>1, cy = y>>1;
    float wrow[6];
#pragma unroll
    for (int m = 0; m < 6; m++) {
        int cx = 4*q - 1 + m;
        wrow[m] = ((unsigned)cx < 96u) ? g_W1[(cz*96 + cy)*96 + cx] : 0.0f;
    }
    float wym4[4], wyp4[4], wzm4[4], wzp4[4];
    int cym = (y-1)>>1, cyp = (y+1)>>1, czm = (z-1)>>1, czp = (z+1)>>1;
#pragma unroll
    for (int m = 0; m < 4; m++) {
        int cx = 4*q + m;
        wym4[m] = (y > 0)    ? g_W1[(cz*96 + cym)*96 + cx] : 0.0f;
        wyp4[m] = (y < HH-1) ? g_W1[(cz*96 + cyp)*96 + cx] : 0.0f;
        wzm4[m] = (z > 0)    ? g_W1[(czm*96 + cy)*96 + cx] : 0.0f;
        wzp4[m] = (z < DD-1) ? g_W1[(czp*96 + cy)*96 + cx] : 0.0f;
    }

    float ra[10], rym[8], ryp[8], rzm[8], rzp[8], pcen[8];
    SPREAD10(ra, r_xm, r_c0, r_c1, r_xp);
    SPREAD8(rym, r_ym0, r_ym1); SPREAD8(ryp, r_yp0, r_yp1);
    SPREAD8(rzm, r_zm0, r_zm1); SPREAD8(rzp, r_zp0, r_zp1);
    SPREAD8(pcen, p_c0, p_c1);

    float pp[8], rr[8];
#pragma unroll
    for (int j = 0; j < 8; j++) {
        float dc  = -wrow[j/2 + 1]                    - ra[j+1]*INVD;
        float dxm = -wrow[(j==0) ? 0 : ((j-1)/2 + 1)] - ra[j]  *INVD;
        float dxp = -wrow[(j+1)/2 + 1]                - ra[j+2]*INVD;
        float dym = -wym4[j/2] - rym[j]*INVD;
        float dyp = -wyp4[j/2] - ryp[j]*INVD;
        float dzm = -wzm4[j/2] - rzm[j]*INVD;
        float dzp = -wzp4[j/2] - rzp[j]*INVD;
        float lapd = dxm + dxp + dym + dyp + dzm + dzp - 6.0f*dc;
        pp[j] = pcen[j] + dc;
        rr[j] = lapd + ra[j+1];
    }
    g_P4[i4]    = make_float4(pp[0], pp[1], pp[2], pp[3]);
    g_P4[i4+1]  = make_float4(pp[4], pp[5], pp[6], pp[7]);
    g_R0b4[i4]  = make_float4(rr[0], rr[1], rr[2], rr[3]);
    g_R0b4[i4+1]= make_float4(rr[4], rr[5], rr[6], rr[7]);
}

// -------- fused iter-2 p-update + final projection + sb [R4 form] --------
__global__ __launch_bounds__(192) void k_pfinal(float* __restrict__ out_p, float* __restrict__ out_wmg,
                                                float* __restrict__ ou, float* __restrict__ ov,
                                                float* __restrict__ ow) {
    const float* P  = (const float*)g_P4;
    const float* R0 = (const float*)g_R0b4;
    int x4 = threadIdx.x, y = blockIdx.x*4 + threadIdx.y, z = blockIdx.y;
    int i4 = (z*HH + y)*W4N + x4;

    St sp = gather(P, z, y, x4);
    St sr = gather(R0, z, y, x4);
    float4 u4 = g_U4[i4], v4 = g_V4[i4], w4 = g_W4[i4], inv4 = g_INV4[i4];

    float4 op4, owm4, ou4, ov4, ow4;
#pragma unroll
    for (int k = 0; k < 4; k++) {
        int x = 4*x4 + k;
        NBRS(sp, k, pc, pxm, pxp, pym, pyp, pzm, pzp);
        NBRS(sr, k, rc, rxm, rxp, rym, ryp, rzm, rzp);

        float wm   = wmat(g_W1, z, y, x);
        float p2c  = pc  - wm                    - rc  * INVD;
        float p2xm = pxm - wmat(g_W1, z, y, x-1) - rxm * INVD;
        float p2xp = pxp - wmat(g_W1, z, y, x+1) - rxp * INVD;
        float p2ym = pym - wmat(g_W1, z, y-1, x) - rym * INVD;
        float p2yp = pyp - wmat(g_W1, z, y+1, x) - ryp * INVD;
        float p2zm = pzm - wmat(g_W1, z-1, y, x) - rzm * INVD;
        float p2zp = pzp - wmat(g_W1, z+1, y, x) - rzp * INVD;

        float dxp = 0.5f*(p2xp - p2xm);
        float dyp = 0.5f*(p2yp - p2ym);
        float dzp = 0.5f*(p2zp - p2zm);

        float invc = g(inv4, k);
        setk(op4, k, p2c);
        setk(owm4, k, wm);
        setk(ou4, k, (g(u4,k) - dxp*DT) * invc);
        setk(ov4, k, (g(v4,k) - dyp*DT) * invc);
        setk(ow4, k, (g(w4,k) - dzp*DT) * invc);
    }
    ((float4*)out_p)[i4]   = op4;
    ((float4*)out_wmg)[i4] = owm4;
    ((float4*)ou)[i4] = ou4;
    ((float4*)ov)[i4] = ov4;
    ((float4*)ow)[i4] = ow4;
}

// ---------------- launch ----------------
extern "C" void kernel_launch(void* const* d_in, const int* in_sizes, int n_in,
                              void* d_out, int out_size) {
    const float* vu = (const float*)d_in[0];
    const float* vv = (const float*)d_in[1];
    const float* vw = (const float*)d_in[2];
    const float* vp = (const float*)d_in[3];
    const float* sg = (const float*)d_in[4];

    float* out     = (float*)d_out;
    float* out_u   = out;
    float* out_v   = out + (size_t)NFULL;
    float* out_w   = out + (size_t)2*NFULL;
    float* out_p   = out + (size_t)3*NFULL;
    float* out_wmg = out + (size_t)4*NFULL;
    float* out_r   = out + (size_t)5*NFULL;

    void *pR0, *pR0b, *pR1, *pR2, *pR3, *pW2, *pW1;
    cudaGetSymbolAddress(&pR0,  g_R04);
    cudaGetSymbolAddress(&pR0b, g_R0b4);
    cudaGetSymbolAddress(&pR1,  g_R1);
    cudaGetSymbolAddress(&pR2,  g_R2);
    cudaGetSymbolAddress(&pR3,  g_R3);
    cudaGetSymbolAddress(&pW2,  g_W2);
    cudaGetSymbolAddress(&pW1,  g_W1);

    dim3 blk(W4N, 4, 1);          // 192 threads (x4 kernels)
    dim3 grd(HH/4, DD);
    dim3 blk8(X8N, 8, 1);         // 192 threads (x8 kernels)
    dim3 grd8(HH/8, DD);          // 2304 blocks

    k_inv   <<<(NQ+255)/256, 256>>>((const float4*)sg);
    k_pred  <<<grd, blk>>>(vu, vv, vw, vp);
    k_stage3<<<grd, blk>>>(vu, vv, vw, vp);

    // ---- MG iteration 1 (p = vp) ----
    k_residb<<<grd8, blk8>>>(vp);
    k_restrict<<<(NL1+255)/256, 256>>>((const float*)pR0, (float*)pR1, 48, 96, 96);
    k_restrict<<<(NL2+255)/256, 256>>>((const float*)pR1, (float*)pR2, 24, 48, 48);
    k_restrict<<<(NL3+255)/256, 256>>>((const float*)pR2, (float*)pR3, 12, 24, 24);
    k_smooth<<<(NL2+255)/256, 256>>>((const float*)pR3, (const float*)pR2, (float*)pW2,
                                     24, 48, 48, INVD);
    k_smooth<<<(NL1+255)/256, 256>>>((const float*)pW2, (const float*)pR1, (float*)pW1,
                                     48, 96, 96, 1.0f);

    // ---- fused: P = p1; R0b = lap(d) + r0 ----
    k_pup_resid<<<grd8, blk8>>>(vp);

    // ---- MG iteration 2 coarse solve ----
    k_restrict<<<(NL1+255)/256, 256>>>((const float*)pR0b, (float*)pR1, 48, 96, 96);
    k_restrict<<<(NL2+255)/256, 256>>>((const float*)pR1, (float*)pR2, 24, 48, 48);
    k_restrict<<<(NL3+255)/256, 256>>>((const float*)pR2, (float*)pR3, 12, 24, 24);
    k_smooth<<<(NL2+255)/256, 256>>>((const float*)pR3, (const float*)pR2, (float*)pW2,
                                     24, 48, 48, INVD);
    k_smooth<<<(NL1+255)/256, 256>>>((const float*)pW2, (const float*)pR1, (float*)pW1,
                                     48, 96, 96, 1.0f);

    k_pfinal<<<grd, blk>>>(out_p, out_wmg, out_u, out_v, out_w);
    cudaMemcpyAsync(out_r, pR3, NL3*sizeof(float), cudaMemcpyDeviceToDevice);
}